// round 14
// baseline (speedup 1.0000x reference)
#include <cuda_runtime.h>
#include <cstdint>

// ============================================================================
// AdditiveAttention fused kernels for GB300 (sm_103a) — Round 13
//   proj: work-queue + cp.async double-buffered tiles (no register prefetch,
//         no transpose: X kept row-major, A read as float4-over-k broadcast)
//   attn: R12 config (QT=16, 256 thr, split-K S=8, smem-broadcast AV)
// ============================================================================

#define NEG_FILL (-1e6f)
#define S_SPLIT 8
#define QT 16
#define KT 32
#define KP 132

#define NQCHUNK 64             // 2048 q rows / 32
#define NCHUNK  320            // 64 q chunks + 256 k chunks (8192 rows / 32)

// Scratch (allocation-free: __device__ globals; zero-init at module load)
__device__ float g_qh[8 * 256 * 128];                 // 1 MB
__device__ float g_kh[8 * 1024 * 128];                // 4 MB
__device__ float g_po[S_SPLIT * 2048 * 128];          // 8 MB partial o
__device__ float g_pl[S_SPLIT * 2048];                // 64 KB partial l
__device__ int   g_ctr = 0;                           // proj work-queue head

__device__ __forceinline__ float fast_tanh(float x) {
    float y;
    asm("tanh.approx.f32 %0, %1;" : "=f"(y) : "f"(x));
    return y;
}
__device__ __forceinline__ void cp16(uint32_t s, const void* g) {
    asm volatile("cp.async.cg.shared.global [%0], [%1], 16;" :: "r"(s), "l"(g));
}
#define CP_COMMIT() asm volatile("cp.async.commit_group;")
#define CP_WAIT0()  asm volatile("cp.async.wait_group 0;")

// ----------------------------------------------------------------------------
// Projection GEMM, dynamic work queue + cp.async pipeline.
// Chunk = 32 output rows x 128 cols, K=256.  chunks 0..63 -> q rows,
// 64..319 -> k rows (32 per batch; masked chunks skipped in ~1 pull).
// Block = 256 threads (8 warps), 4x4 microtile:
//   ty = tid>>5 -> rows ty*4..+3 (warp-constant -> broadcast A reads)
//   tx = tid&31 -> cols tx*4..+3 (conflict-free LDS.128 B reads)
// smem (floats):  Xs[2][32][20] @ 0 (1280)   row-major, 80B row stride
//                 Ws[2][16][128] @ 1280 (4096)      total 5376 fl = 21504 B
// ----------------------------------------------------------------------------
__global__ __launch_bounds__(256) void proj_kernel(
    const float* __restrict__ Xq, const float* __restrict__ Xk,
    const float* __restrict__ Wq, const float* __restrict__ Wk,
    const int* __restrict__ valid_lens)
{
    __shared__ float sm[5376];
    __shared__ int   s_chunk;

    int tid = threadIdx.x;
    int tx = tid & 31;              // cols tx*4..+3
    int ty = tid >> 5;              // rows ty*4..+3 (== warp id)

    uint32_t su = (uint32_t)__cvta_generic_to_shared(sm);

    // cp.async mapping
    //  X tile 32x16 fl = 128 x 16B chunks: tid<128 -> row=tid>>2, ch=tid&3
    //  W tile 16x128 fl = 512 x 16B chunks: row=tid>>4, ch=tid&15 (+16)
    int xrow = tid >> 2;            // 0..63 (only <32 used when tid<128)
    int xch  = tid & 3;             // 0..3
    int wrow = tid >> 4;            // 0..15
    int wch  = tid & 15;            // 0..15

    uint32_t xdst = su + (uint32_t)(xrow * 20 + xch * 4) * 4u;          // buf0
    uint32_t wdst = su + (uint32_t)(1280 + wrow * 128 + wch * 4) * 4u;  // buf0
    const uint32_t XBUF = 640u * 4u;    // bytes between X buffers
    const uint32_t WBUF = 2048u * 4u;   // bytes between W buffers

    while (true) {
        if (tid == 0) s_chunk = atomicAdd(&g_ctr, 1);
        __syncthreads();
        int c = s_chunk;
        __syncthreads();            // all read s_chunk; prior chunk compute done
        if (c >= NCHUNK) return;

        const float* X; const float* W; float* Y; int row0;
        if (c < NQCHUNK) {
            X = Xq; W = Wq; Y = g_qh; row0 = c << 5;
        } else {
            int kc = c - NQCHUNK;           // 0..255, 32 per batch
            int b  = kc >> 5;
            if (((kc & 31) << 5) >= valid_lens[b]) continue;  // never read
            X = Xk; W = Wk; Y = g_kh; row0 = kc << 5;
        }

        const float* Xg = &X[(row0 + xrow) * 256 + xch * 4];  // + k0
        const float* Wg = &W[wrow * 128 + wch * 4];           // + k0*128

        // prologue: k-tile 0 -> buf 0
        if (tid < 128) cp16(xdst, Xg);
        cp16(wdst,        Wg);
        cp16(wdst + 256u, Wg + 64);      // cols +64 -> 64 floats = 256B
        CP_COMMIT();

        float acc[4][4];
#pragma unroll
        for (int i = 0; i < 4; i++)
#pragma unroll
            for (int j = 0; j < 4; j++) acc[i][j] = 0.f;

        for (int it = 0; it < 16; it++) {
            int buf = it & 1;
            CP_WAIT0();
            __syncthreads();

            if (it < 15) {          // issue next k-tile into other buffer
                int k0 = (it + 1) << 4;
                uint32_t xo = (buf ^ 1) ? XBUF : 0u;
                uint32_t wo = (buf ^ 1) ? WBUF : 0u;
                if (tid < 128) cp16(xdst + xo, Xg + k0);
                cp16(wdst + wo,        Wg + k0 * 128);
                cp16(wdst + wo + 256u, Wg + k0 * 128 + 64);
            }
            CP_COMMIT();

            const float* xb = sm + buf * 640 + ty * 80;          // 4 rows x 20
            const float* wb = sm + 1280 + buf * 2048 + tx * 4;
#pragma unroll
            for (int kk = 0; kk < 16; kk += 4) {
                float4 a0 = *(float4*)&xb[kk];          // row ty*4+0, k kk..+3
                float4 a1 = *(float4*)&xb[20 + kk];
                float4 a2 = *(float4*)&xb[40 + kk];
                float4 a3 = *(float4*)&xb[60 + kk];
                float4 b0 = *(float4*)&wb[(kk + 0) * 128];
                float4 b1 = *(float4*)&wb[(kk + 1) * 128];
                float4 b2 = *(float4*)&wb[(kk + 2) * 128];
                float4 b3 = *(float4*)&wb[(kk + 3) * 128];
                // k = kk+0 (a*.x, b0)
                acc[0][0] += a0.x * b0.x; acc[0][1] += a0.x * b0.y;
                acc[0][2] += a0.x * b0.z; acc[0][3] += a0.x * b0.w;
                acc[1][0] += a1.x * b0.x; acc[1][1] += a1.x * b0.y;
                acc[1][2] += a1.x * b0.z; acc[1][3] += a1.x * b0.w;
                acc[2][0] += a2.x * b0.x; acc[2][1] += a2.x * b0.y;
                acc[2][2] += a2.x * b0.z; acc[2][3] += a2.x * b0.w;
                acc[3][0] += a3.x * b0.x; acc[3][1] += a3.x * b0.y;
                acc[3][2] += a3.x * b0.z; acc[3][3] += a3.x * b0.w;
                // k = kk+1 (a*.y, b1)
                acc[0][0] += a0.y * b1.x; acc[0][1] += a0.y * b1.y;
                acc[0][2] += a0.y * b1.z; acc[0][3] += a0.y * b1.w;
                acc[1][0] += a1.y * b1.x; acc[1][1] += a1.y * b1.y;
                acc[1][2] += a1.y * b1.z; acc[1][3] += a1.y * b1.w;
                acc[2][0] += a2.y * b1.x; acc[2][1] += a2.y * b1.y;
                acc[2][2] += a2.y * b1.z; acc[2][3] += a2.y * b1.w;
                acc[3][0] += a3.y * b1.x; acc[3][1] += a3.y * b1.y;
                acc[3][2] += a3.y * b1.z; acc[3][3] += a3.y * b1.w;
                // k = kk+2 (a*.z, b2)
                acc[0][0] += a0.z * b2.x; acc[0][1] += a0.z * b2.y;
                acc[0][2] += a0.z * b2.z; acc[0][3] += a0.z * b2.w;
                acc[1][0] += a1.z * b2.x; acc[1][1] += a1.z * b2.y;
                acc[1][2] += a1.z * b2.z; acc[1][3] += a1.z * b2.w;
                acc[2][0] += a2.z * b2.x; acc[2][1] += a2.z * b2.y;
                acc[2][2] += a2.z * b2.z; acc[2][3] += a2.z * b2.w;
                acc[3][0] += a3.z * b2.x; acc[3][1] += a3.z * b2.y;
                acc[3][2] += a3.z * b2.z; acc[3][3] += a3.z * b2.w;
                // k = kk+3 (a*.w, b3)
                acc[0][0] += a0.w * b3.x; acc[0][1] += a0.w * b3.y;
                acc[0][2] += a0.w * b3.z; acc[0][3] += a0.w * b3.w;
                acc[1][0] += a1.w * b3.x; acc[1][1] += a1.w * b3.y;
                acc[1][2] += a1.w * b3.z; acc[1][3] += a1.w * b3.w;
                acc[2][0] += a2.w * b3.x; acc[2][1] += a2.w * b3.y;
                acc[2][2] += a2.w * b3.z; acc[2][3] += a2.w * b3.w;
                acc[3][0] += a3.w * b3.x; acc[3][1] += a3.w * b3.y;
                acc[3][2] += a3.w * b3.z; acc[3][3] += a3.w * b3.w;
            }
        }

#pragma unroll
        for (int i = 0; i < 4; i++) {
            int r = row0 + ty * 4 + i;
            float4 o = {acc[i][0], acc[i][1], acc[i][2], acc[i][3]};
            *(float4*)&Y[r * 128 + tx * 4] = o;
        }
        // next pull's double-sync protects buffer reuse and s_chunk
    }
}

// ----------------------------------------------------------------------------
// Split-K score + exp + AV partial kernel, cp.async double-buffered.
// grid = (Q/QT=16, B, S_SPLIT), 256 threads, 8 warps, 2 q-rows per warp.
// AV uses a per-warp smem p-strip with float4 broadcast reads (no shfl).
// Dynamic smem layout (floats):
//   ks[2][32][132] @ 0        (8448)
//   vs[2][32][128] @ 8448     (8192)
//   qs[16][128]    @ 16640    (2048)
//   wv[128]        @ 18688    (128)
//   pb[8][2][32]   @ 18816    (512)    total 19328 floats = 77312 B
// ----------------------------------------------------------------------------
#define ATTN_SMEM_BYTES 77312

__global__ __launch_bounds__(256) void attn_partial_kernel(
    const float* __restrict__ V, const int* __restrict__ valid_lens,
    const float* __restrict__ w_v)
{
    extern __shared__ float sm[];
    float* qs = sm + 16640;
    float* wv = sm + 18688;
    float* pb = sm + 18816;

    int b    = blockIdx.y;
    int q0   = blockIdx.x * QT;
    int sp   = blockIdx.z;
    int tid  = threadIdx.x;
    int w    = tid >> 5;
    int lane = tid & 31;
    int nv   = valid_lens[b];          // 1..1024
    int ntiles = (nv + 31) >> 5;

    uint32_t su = (uint32_t)__cvta_generic_to_shared(sm);

    int lr = tid >> 3;                 // 0..31
    int lc = (tid & 7) << 2;           // float col base
    const float* gkb = g_kh + ((size_t)(b << 10) + lr) * 128 + lc;
    const float* gvb = V    + ((size_t)(b << 10) + lr) * 128 + lc;
    uint32_t ku0 = su + (uint32_t)(lr * KP  + lc) * 4u;
    uint32_t vu0 = su + (uint32_t)(8448 + lr * 128 + lc) * 4u;

    // prologue: issue tile sp into buf 0
    if (sp < ntiles) {
        const float* gk = gkb + (sp << 5) * 128;
        const float* gv = gvb + (sp << 5) * 128;
#pragma unroll
        for (int j = 0; j < 4; j++) {
            cp16(ku0 + j * 128u, gk + (j << 3) * 4);
            cp16(vu0 + j * 128u, gv + (j << 3) * 4);
        }
    }
    CP_COMMIT();

    // stage 16 q rows + w_v (overlaps with cp.async)
    {
        int r = tid >> 4;              // 0..15
        int c = (tid & 15) << 3;       // 0,8,...,120
        const float* src = &g_qh[((b << 8) + q0 + r) * 128 + c];
        *(float4*)&qs[r * 128 + c]     = *(const float4*)(src);
        *(float4*)&qs[r * 128 + c + 4] = *(const float4*)(src + 4);
    }
    if (tid < 128) wv[tid] = w_v[tid];

    float  l0 = 0.f, l1 = 0.f;
    float4 o0 = {0.f, 0.f, 0.f, 0.f};
    float4 o1 = {0.f, 0.f, 0.f, 0.f};

    const float* qsp0 = qs + (2 * w)     * 128;
    const float* qsp1 = qs + (2 * w + 1) * 128;
    float* pw = pb + w * 64;           // [2][32] strip for this warp

    int buf = 0;
    for (int t = sp; t < ntiles; t += S_SPLIT, buf ^= 1) {
        CP_WAIT0();
        __syncthreads();

        int tn = t + S_SPLIT;
        if (tn < ntiles) {
            uint32_t koff = (buf ^ 1) ? 0x4200u : 0u;   // 4224 floats * 4B
            uint32_t voff = (buf ^ 1) ? 0x4000u : 0u;   // 4096 floats * 4B
            const float* gk = gkb + (tn << 5) * 128;
            const float* gv = gvb + (tn << 5) * 128;
#pragma unroll
            for (int j = 0; j < 4; j++) {
                cp16(ku0 + koff + j * 128u, gk + (j << 3) * 4);
                cp16(vu0 + voff + j * 128u, gv + (j << 3) * 4);
            }
        }
        CP_COMMIT();

        // ---- scores for k = (t<<5) + lane, q rows 2w and 2w+1 ----
        const float* ksp = sm + buf * 4224 + lane * KP;
        float s0 = 0.f, s1 = 0.f;
#pragma unroll
        for (int h = 0; h < 128; h += 4) {
            float4 kv = *(float4*)&ksp[h];
            float4 w4 = *(float4*)&wv[h];
            float4 qa = *(float4*)&qsp0[h];
            float4 qb = *(float4*)&qsp1[h];
            s0 += fast_tanh(qa.x + kv.x) * w4.x;
            s1 += fast_tanh(qb.x + kv.x) * w4.x;
            s0 += fast_tanh(qa.y + kv.y) * w4.y;
            s1 += fast_tanh(qb.y + kv.y) * w4.y;
            s0 += fast_tanh(qa.z + kv.z) * w4.z;
            s1 += fast_tanh(qb.z + kv.z) * w4.z;
            s0 += fast_tanh(qa.w + kv.w) * w4.w;
            s1 += fast_tanh(qb.w + kv.w) * w4.w;
        }
        if ((t << 5) + lane >= nv) { s0 = NEG_FILL; s1 = NEG_FILL; }

        float p0 = __expf(s0);
        float p1 = __expf(s1);
        l0 += p0; l1 += p1;

        // publish p to the warp strip, then broadcast-read as float4
        pw[lane]      = p0;
        pw[32 + lane] = p1;
        __syncwarp();

        // ---- AV: one V read + one p4 pair per 4 k-steps ----
        const float* vsp = sm + 8448 + buf * 4096 + (lane << 2);
#pragma unroll
        for (int g = 0; g < 8; g++) {
            float4 pa = *(float4*)&pw[g * 4];
            float4 pc = *(float4*)&pw[32 + g * 4];
            float4 v0 = *(float4*)&vsp[(g * 4 + 0) * 128];
            float4 v1 = *(float4*)&vsp[(g * 4 + 1) * 128];
            float4 v2 = *(float4*)&vsp[(g * 4 + 2) * 128];
            float4 v3 = *(float4*)&vsp[(g * 4 + 3) * 128];
            o0.x += pa.x * v0.x; o0.y += pa.x * v0.y;
            o0.z += pa.x * v0.z; o0.w += pa.x * v0.w;
            o1.x += pc.x * v0.x; o1.y += pc.x * v0.y;
            o1.z += pc.x * v0.z; o1.w += pc.x * v0.w;
            o0.x += pa.y * v1.x; o0.y += pa.y * v1.y;
            o0.z += pa.y * v1.z; o0.w += pa.y * v1.w;
            o1.x += pc.y * v1.x; o1.y += pc.y * v1.y;
            o1.z += pc.y * v1.z; o1.w += pc.y * v1.w;
            o0.x += pa.z * v2.x; o0.y += pa.z * v2.y;
            o0.z += pa.z * v2.z; o0.w += pa.z * v2.w;
            o1.x += pc.z * v2.x; o1.y += pc.z * v2.y;
            o1.z += pc.z * v2.z; o1.w += pc.z * v2.w;
            o0.x += pa.w * v3.x; o0.y += pa.w * v3.y;
            o0.z += pa.w * v3.z; o0.w += pa.w * v3.w;
            o1.x += pc.w * v3.x; o1.y += pc.w * v3.y;
            o1.z += pc.w * v3.z; o1.w += pc.w * v3.w;
        }
    }

#pragma unroll
    for (int off = 16; off; off >>= 1) {
        l0 += __shfl_xor_sync(0xffffffffu, l0, off);
        l1 += __shfl_xor_sync(0xffffffffu, l1, off);
    }

    int row0 = (b << 8) + q0 + 2 * w;
    if (lane == 0) {
        g_pl[sp * 2048 + row0]     = l0;
        g_pl[sp * 2048 + row0 + 1] = l1;
    }
    *(float4*)&g_po[(sp * 2048 + row0) * 128 + (lane << 2)]       = o0;
    *(float4*)&g_po[(sp * 2048 + row0 + 1) * 128 + (lane << 2)]   = o1;
}

// ----------------------------------------------------------------------------
// Combine partials: out[row,:] = sum_s o_s / sum_s l_s.
// Also resets the proj work-queue counter for the next graph replay.
// ----------------------------------------------------------------------------
__global__ __launch_bounds__(256) void combine_kernel(float* __restrict__ out)
{
    if (blockIdx.x == 0 && threadIdx.x == 0) g_ctr = 0;   // queue reset

    int idx = blockIdx.x * 256 + threadIdx.x;   // 0 .. 65535
    int row = idx >> 5;
    int c   = (idx & 31) << 2;

    float  l = 0.f;
    float4 a = {0.f, 0.f, 0.f, 0.f};
#pragma unroll
    for (int s = 0; s < S_SPLIT; s++) {
        l += g_pl[s * 2048 + row];
        float4 v = *(const float4*)&g_po[(s * 2048 + row) * 128 + c];
        a.x += v.x; a.y += v.y; a.z += v.z; a.w += v.w;
    }
    float inv = 1.0f / l;
    a.x *= inv; a.y *= inv; a.z *= inv; a.w *= inv;
    *(float4*)&out[row * 128 + c] = a;
}

// ----------------------------------------------------------------------------
// Launch
// ----------------------------------------------------------------------------
extern "C" void kernel_launch(void* const* d_in, const int* in_sizes, int n_in,
                              void* d_out, int out_size)
{
    const float* queries    = (const float*)d_in[0];  // [8,256,256]
    const float* keys       = (const float*)d_in[1];  // [8,1024,256]
    const float* values     = (const float*)d_in[2];  // [8,1024,128]
    const int*   valid_lens = (const int*)  d_in[3];  // [8]
    const float* W_q        = (const float*)d_in[4];  // [256,128]
    const float* W_k        = (const float*)d_in[5];  // [256,128]
    const float* w_v        = (const float*)d_in[6];  // [128]
    float*       out        = (float*)d_out;          // [8,256,128]

    cudaFuncSetAttribute(attn_partial_kernel,
                         cudaFuncAttributeMaxDynamicSharedMemorySize,
                         ATTN_SMEM_BYTES);

    // 592 worker blocks (4/SM), each pulls 32-row chunks until queue empty
    proj_kernel<<<592, 256>>>(queries, keys, W_q, W_k, valid_lens);

    dim3 grid(256 / QT, 8, S_SPLIT);
    attn_partial_kernel<<<grid, 256, ATTN_SMEM_BYTES>>>(values, valid_lens, w_v);

    combine_kernel<<<256, 256>>>(out);
}

// round 15
// speedup vs baseline: 1.2478x; 1.2478x over previous
#include <cuda_runtime.h>
#include <cstdint>

// ============================================================================
// AdditiveAttention fused kernels for GB300 (sm_103a) — Round 15
//   proj: TF32 tensor-core GEMM (mma.sync.m16n8k8) on the work-queue +
//         cp.async double-buffer skeleton. Conflict-free fragment strides.
//   attn: R12 config (QT=16, 256 thr, split-K S=8, smem-broadcast AV)
// ============================================================================

#define NEG_FILL (-1e6f)
#define S_SPLIT 8
#define QT 16
#define KT 32
#define KP 132

#define NQCHUNK 64             // 2048 q rows / 32
#define NCHUNK  320            // 64 q chunks + 256 k chunks (8192 rows / 32)

// Scratch (allocation-free: __device__ globals; zero-init at module load)
__device__ float g_qh[8 * 256 * 128];                 // 1 MB
__device__ float g_kh[8 * 1024 * 128];                // 4 MB
__device__ float g_po[S_SPLIT * 2048 * 128];          // 8 MB partial o
__device__ float g_pl[S_SPLIT * 2048];                // 64 KB partial l
__device__ int   g_ctr = 0;                           // proj work-queue head

__device__ __forceinline__ float fast_tanh(float x) {
    float y;
    asm("tanh.approx.f32 %0, %1;" : "=f"(y) : "f"(x));
    return y;
}
__device__ __forceinline__ void cp16(uint32_t s, const void* g) {
    asm volatile("cp.async.cg.shared.global [%0], [%1], 16;" :: "r"(s), "l"(g));
}
#define CP_COMMIT() asm volatile("cp.async.commit_group;")
#define CP_WAIT0()  asm volatile("cp.async.wait_group 0;")

__device__ __forceinline__ uint32_t f2tf32(float x) {
    uint32_t r;
    asm("cvt.rna.tf32.f32 %0, %1;" : "=r"(r) : "f"(x));
    return r;
}
__device__ __forceinline__ void mma_tf32(
    float& d0, float& d1, float& d2, float& d3,
    uint32_t a0, uint32_t a1, uint32_t a2, uint32_t a3,
    uint32_t b0, uint32_t b1)
{
    asm("mma.sync.aligned.m16n8k8.row.col.f32.tf32.tf32.f32 "
        "{%0,%1,%2,%3},{%4,%5,%6,%7},{%8,%9},{%0,%1,%2,%3};"
        : "+f"(d0), "+f"(d1), "+f"(d2), "+f"(d3)
        : "r"(a0), "r"(a1), "r"(a2), "r"(a3), "r"(b0), "r"(b1));
}

// ----------------------------------------------------------------------------
// Projection GEMM, TF32 tensor cores + work queue + cp.async pipeline.
// Chunk = 32 output rows x 128 cols, K=256. chunks 0..63 -> q, 64..319 -> k
// (32 per batch; masked chunks skipped in ~1 pull).
// Block = 256 threads (8 warps). Warp w: rows (w>>2)*16..+15,
// cols (w&3)*32..+31 (4 mma n-tiles of 8). K-tile = 32 (4 mma k8-steps).
// smem (floats): Xs[2][32][36] @ 0 (2304)      A-frag banks 4*gid+t4: CF
//                Ws[2][32][136] @ 2304 (8704)  B-frag banks 8*t4+gid: CF
//                total 11008 floats = 44032 B
// ----------------------------------------------------------------------------
__global__ __launch_bounds__(256) void proj_kernel(
    const float* __restrict__ Xq, const float* __restrict__ Xk,
    const float* __restrict__ Wq, const float* __restrict__ Wk,
    const int* __restrict__ valid_lens)
{
    __shared__ float sm[11008];
    __shared__ int   s_chunk;

    int tid  = threadIdx.x;
    int w    = tid >> 5;
    int lane = tid & 31;
    int gid  = lane >> 2;           // 0..7
    int t4   = lane & 3;            // 0..3
    int rowbase = (w >> 2) << 4;    // 0 or 16
    int ncol0   = (w & 3) << 5;     // 0,32,64,96

    uint32_t su = (uint32_t)__cvta_generic_to_shared(sm);

    // cp.async mapping
    // X k-tile: 32 rows x 32 floats = 256 chunks, 1/thread
    int xrow  = tid >> 3;           // 0..31
    int xcol4 = (tid & 7) << 2;     // 0..28
    uint32_t xdst = su + (uint32_t)(xrow * 36 + xcol4) * 4u;
    // W k-tile: 32 rows x 128 floats = 1024 chunks, 4/thread
    int wrow[4], wcol4[4];
    uint32_t wdst[4];
#pragma unroll
    for (int j = 0; j < 4; j++) {
        int id = tid + (j << 8);
        wrow[j]  = id >> 5;         // 0..31
        wcol4[j] = (id & 31) << 2;  // 0..124
        wdst[j]  = su + (uint32_t)(2304 + wrow[j] * 136 + wcol4[j]) * 4u;
    }
    const uint32_t XB = 1152u * 4u;   // bytes between X buffers
    const uint32_t WB = 4352u * 4u;   // bytes between W buffers

    while (true) {
        if (tid == 0) s_chunk = atomicAdd(&g_ctr, 1);
        __syncthreads();
        int c = s_chunk;
        __syncthreads();            // all read s_chunk; prior chunk compute done
        if (c >= NCHUNK) return;

        const float* X; const float* W; float* Y; int row0;
        if (c < NQCHUNK) {
            X = Xq; W = Wq; Y = g_qh; row0 = c << 5;
        } else {
            int kc = c - NQCHUNK;           // 0..255, 32 per batch
            int b  = kc >> 5;
            if (((kc & 31) << 5) >= valid_lens[b]) continue;  // never read
            X = Xk; W = Wk; Y = g_kh; row0 = kc << 5;
        }

        const float* Xg = &X[(row0 + xrow) * 256 + xcol4];  // + k0

        // prologue: k-tile 0 -> buf 0
        cp16(xdst, Xg);
#pragma unroll
        for (int j = 0; j < 4; j++)
            cp16(wdst[j], &W[wrow[j] * 128 + wcol4[j]]);
        CP_COMMIT();

        float d[4][4];
#pragma unroll
        for (int j = 0; j < 4; j++)
#pragma unroll
            for (int i = 0; i < 4; i++) d[j][i] = 0.f;

        for (int it = 0; it < 8; it++) {
            int buf = it & 1;
            CP_WAIT0();
            __syncthreads();

            if (it < 7) {           // issue next k-tile into other buffer
                int k0 = (it + 1) << 5;
                uint32_t xo = (buf ^ 1) ? XB : 0u;
                uint32_t wo = (buf ^ 1) ? WB : 0u;
                cp16(xdst + xo, Xg + k0);
#pragma unroll
                for (int j = 0; j < 4; j++)
                    cp16(wdst[j] + wo, &W[(k0 + wrow[j]) * 128 + wcol4[j]]);
            }
            CP_COMMIT();

            const float* xb = sm + buf * 1152;
            const float* wb = sm + 2304 + buf * 4352;
            int ra = rowbase + gid;
#pragma unroll
            for (int kk = 0; kk < 32; kk += 8) {
                uint32_t a0 = f2tf32(xb[ra * 36 + kk + t4]);
                uint32_t a1 = f2tf32(xb[(ra + 8) * 36 + kk + t4]);
                uint32_t a2 = f2tf32(xb[ra * 36 + kk + t4 + 4]);
                uint32_t a3 = f2tf32(xb[(ra + 8) * 36 + kk + t4 + 4]);
#pragma unroll
                for (int j = 0; j < 4; j++) {
                    int col = ncol0 + (j << 3) + gid;
                    uint32_t b0 = f2tf32(wb[(kk + t4) * 136 + col]);
                    uint32_t b1 = f2tf32(wb[(kk + t4 + 4) * 136 + col]);
                    mma_tf32(d[j][0], d[j][1], d[j][2], d[j][3],
                             a0, a1, a2, a3, b0, b1);
                }
            }
        }

        // epilogue: D fragments -> Y
        {
            int rhi = row0 + rowbase + gid;
#pragma unroll
            for (int j = 0; j < 4; j++) {
                int col = ncol0 + (j << 3) + (t4 << 1);
                float2 lo = {d[j][0], d[j][1]};
                float2 hi = {d[j][2], d[j][3]};
                *(float2*)&Y[rhi * 128 + col]       = lo;
                *(float2*)&Y[(rhi + 8) * 128 + col] = hi;
            }
        }
        // next pull's double-sync protects buffer reuse and s_chunk
    }
}

// ----------------------------------------------------------------------------
// Split-K score + exp + AV partial kernel, cp.async double-buffered.
// grid = (Q/QT=16, B, S_SPLIT), 256 threads, 8 warps, 2 q-rows per warp.
// AV uses a per-warp smem p-strip with float4 broadcast reads (no shfl).
// Dynamic smem layout (floats):
//   ks[2][32][132] @ 0        (8448)
//   vs[2][32][128] @ 8448     (8192)
//   qs[16][128]    @ 16640    (2048)
//   wv[128]        @ 18688    (128)
//   pb[8][2][32]   @ 18816    (512)    total 19328 floats = 77312 B
// ----------------------------------------------------------------------------
#define ATTN_SMEM_BYTES 77312

__global__ __launch_bounds__(256) void attn_partial_kernel(
    const float* __restrict__ V, const int* __restrict__ valid_lens,
    const float* __restrict__ w_v)
{
    extern __shared__ float sm[];
    float* qs = sm + 16640;
    float* wv = sm + 18688;
    float* pb = sm + 18816;

    int b    = blockIdx.y;
    int q0   = blockIdx.x * QT;
    int sp   = blockIdx.z;
    int tid  = threadIdx.x;
    int w    = tid >> 5;
    int lane = tid & 31;
    int nv   = valid_lens[b];          // 1..1024
    int ntiles = (nv + 31) >> 5;

    uint32_t su = (uint32_t)__cvta_generic_to_shared(sm);

    int lr = tid >> 3;                 // 0..31
    int lc = (tid & 7) << 2;           // float col base
    const float* gkb = g_kh + ((size_t)(b << 10) + lr) * 128 + lc;
    const float* gvb = V    + ((size_t)(b << 10) + lr) * 128 + lc;
    uint32_t ku0 = su + (uint32_t)(lr * KP  + lc) * 4u;
    uint32_t vu0 = su + (uint32_t)(8448 + lr * 128 + lc) * 4u;

    // prologue: issue tile sp into buf 0
    if (sp < ntiles) {
        const float* gk = gkb + (sp << 5) * 128;
        const float* gv = gvb + (sp << 5) * 128;
#pragma unroll
        for (int j = 0; j < 4; j++) {
            cp16(ku0 + j * 128u, gk + (j << 3) * 4);
            cp16(vu0 + j * 128u, gv + (j << 3) * 4);
        }
    }
    CP_COMMIT();

    // stage 16 q rows + w_v (overlaps with cp.async)
    {
        int r = tid >> 4;              // 0..15
        int c = (tid & 15) << 3;       // 0,8,...,120
        const float* src = &g_qh[((b << 8) + q0 + r) * 128 + c];
        *(float4*)&qs[r * 128 + c]     = *(const float4*)(src);
        *(float4*)&qs[r * 128 + c + 4] = *(const float4*)(src + 4);
    }
    if (tid < 128) wv[tid] = w_v[tid];

    float  l0 = 0.f, l1 = 0.f;
    float4 o0 = {0.f, 0.f, 0.f, 0.f};
    float4 o1 = {0.f, 0.f, 0.f, 0.f};

    const float* qsp0 = qs + (2 * w)     * 128;
    const float* qsp1 = qs + (2 * w + 1) * 128;
    float* pw = pb + w * 64;           // [2][32] strip for this warp

    int buf = 0;
    for (int t = sp; t < ntiles; t += S_SPLIT, buf ^= 1) {
        CP_WAIT0();
        __syncthreads();

        int tn = t + S_SPLIT;
        if (tn < ntiles) {
            uint32_t koff = (buf ^ 1) ? 0x4200u : 0u;   // 4224 floats * 4B
            uint32_t voff = (buf ^ 1) ? 0x4000u : 0u;   // 4096 floats * 4B
            const float* gk = gkb + (tn << 5) * 128;
            const float* gv = gvb + (tn << 5) * 128;
#pragma unroll
            for (int j = 0; j < 4; j++) {
                cp16(ku0 + koff + j * 128u, gk + (j << 3) * 4);
                cp16(vu0 + voff + j * 128u, gv + (j << 3) * 4);
            }
        }
        CP_COMMIT();

        // ---- scores for k = (t<<5) + lane, q rows 2w and 2w+1 ----
        const float* ksp = sm + buf * 4224 + lane * KP;
        float s0 = 0.f, s1 = 0.f;
#pragma unroll
        for (int h = 0; h < 128; h += 4) {
            float4 kv = *(float4*)&ksp[h];
            float4 w4 = *(float4*)&wv[h];
            float4 qa = *(float4*)&qsp0[h];
            float4 qb = *(float4*)&qsp1[h];
            s0 += fast_tanh(qa.x + kv.x) * w4.x;
            s1 += fast_tanh(qb.x + kv.x) * w4.x;
            s0 += fast_tanh(qa.y + kv.y) * w4.y;
            s1 += fast_tanh(qb.y + kv.y) * w4.y;
            s0 += fast_tanh(qa.z + kv.z) * w4.z;
            s1 += fast_tanh(qb.z + kv.z) * w4.z;
            s0 += fast_tanh(qa.w + kv.w) * w4.w;
            s1 += fast_tanh(qb.w + kv.w) * w4.w;
        }
        if ((t << 5) + lane >= nv) { s0 = NEG_FILL; s1 = NEG_FILL; }

        float p0 = __expf(s0);
        float p1 = __expf(s1);
        l0 += p0; l1 += p1;

        // publish p to the warp strip, then broadcast-read as float4
        pw[lane]      = p0;
        pw[32 + lane] = p1;
        __syncwarp();

        // ---- AV: one V read + one p4 pair per 4 k-steps ----
        const float* vsp = sm + 8448 + buf * 4096 + (lane << 2);
#pragma unroll
        for (int g = 0; g < 8; g++) {
            float4 pa = *(float4*)&pw[g * 4];
            float4 pc = *(float4*)&pw[32 + g * 4];
            float4 v0 = *(float4*)&vsp[(g * 4 + 0) * 128];
            float4 v1 = *(float4*)&vsp[(g * 4 + 1) * 128];
            float4 v2 = *(float4*)&vsp[(g * 4 + 2) * 128];
            float4 v3 = *(float4*)&vsp[(g * 4 + 3) * 128];
            o0.x += pa.x * v0.x; o0.y += pa.x * v0.y;
            o0.z += pa.x * v0.z; o0.w += pa.x * v0.w;
            o1.x += pc.x * v0.x; o1.y += pc.x * v0.y;
            o1.z += pc.x * v0.z; o1.w += pc.x * v0.w;
            o0.x += pa.y * v1.x; o0.y += pa.y * v1.y;
            o0.z += pa.y * v1.z; o0.w += pa.y * v1.w;
            o1.x += pc.y * v1.x; o1.y += pc.y * v1.y;
            o1.z += pc.y * v1.z; o1.w += pc.y * v1.w;
            o0.x += pa.z * v2.x; o0.y += pa.z * v2.y;
            o0.z += pa.z * v2.z; o0.w += pa.z * v2.w;
            o1.x += pc.z * v2.x; o1.y += pc.z * v2.y;
            o1.z += pc.z * v2.z; o1.w += pc.z * v2.w;
            o0.x += pa.w * v3.x; o0.y += pa.w * v3.y;
            o0.z += pa.w * v3.z; o0.w += pa.w * v3.w;
            o1.x += pc.w * v3.x; o1.y += pc.w * v3.y;
            o1.z += pc.w * v3.z; o1.w += pc.w * v3.w;
        }
    }

#pragma unroll
    for (int off = 16; off; off >>= 1) {
        l0 += __shfl_xor_sync(0xffffffffu, l0, off);
        l1 += __shfl_xor_sync(0xffffffffu, l1, off);
    }

    int row0 = (b << 8) + q0 + 2 * w;
    if (lane == 0) {
        g_pl[sp * 2048 + row0]     = l0;
        g_pl[sp * 2048 + row0 + 1] = l1;
    }
    *(float4*)&g_po[(sp * 2048 + row0) * 128 + (lane << 2)]       = o0;
    *(float4*)&g_po[(sp * 2048 + row0 + 1) * 128 + (lane << 2)]   = o1;
}

// ----------------------------------------------------------------------------
// Combine partials: out[row,:] = sum_s o_s / sum_s l_s.
// Also resets the proj work-queue counter for the next graph replay.
// ----------------------------------------------------------------------------
__global__ __launch_bounds__(256) void combine_kernel(float* __restrict__ out)
{
    if (blockIdx.x == 0 && threadIdx.x == 0) g_ctr = 0;   // queue reset

    int idx = blockIdx.x * 256 + threadIdx.x;   // 0 .. 65535
    int row = idx >> 5;
    int c   = (idx & 31) << 2;

    float  l = 0.f;
    float4 a = {0.f, 0.f, 0.f, 0.f};
#pragma unroll
    for (int s = 0; s < S_SPLIT; s++) {
        l += g_pl[s * 2048 + row];
        float4 v = *(const float4*)&g_po[(s * 2048 + row) * 128 + c];
        a.x += v.x; a.y += v.y; a.z += v.z; a.w += v.w;
    }
    float inv = 1.0f / l;
    a.x *= inv; a.y *= inv; a.z *= inv; a.w *= inv;
    *(float4*)&out[row * 128 + c] = a;
}

// ----------------------------------------------------------------------------
// Launch
// ----------------------------------------------------------------------------
extern "C" void kernel_launch(void* const* d_in, const int* in_sizes, int n_in,
                              void* d_out, int out_size)
{
    const float* queries    = (const float*)d_in[0];  // [8,256,256]
    const float* keys       = (const float*)d_in[1];  // [8,1024,256]
    const float* values     = (const float*)d_in[2];  // [8,1024,128]
    const int*   valid_lens = (const int*)  d_in[3];  // [8]
    const float* W_q        = (const float*)d_in[4];  // [256,128]
    const float* W_k        = (const float*)d_in[5];  // [256,128]
    const float* w_v        = (const float*)d_in[6];  // [128]
    float*       out        = (float*)d_out;          // [8,256,128]

    cudaFuncSetAttribute(attn_partial_kernel,
                         cudaFuncAttributeMaxDynamicSharedMemorySize,
                         ATTN_SMEM_BYTES);

    // 296 worker blocks (2/SM), each pulls 32-row chunks until queue empty
    proj_kernel<<<296, 256>>>(queries, keys, W_q, W_k, valid_lens);

    dim3 grid(256 / QT, 8, S_SPLIT);
    attn_partial_kernel<<<grid, 256, ATTN_SMEM_BYTES>>>(values, valid_lens, w_v);

    combine_kernel<<<256, 256>>>(out);
}